// round 2
// baseline (speedup 1.0000x reference)
#include <cuda_runtime.h>

#define NN   128
#define BB   32
#define INF  4608
#define KSPLIT 9     // 4608 / 512
#define KSEG   512

// ---------------- device scratch (no allocations allowed) ----------------
__device__ float g_Q[NN * NN];            // Q[n][i] = sum_j ev[i][j][n]
__device__ float g_nsum[NN];              // nsum[d] = sum_n ns[n][d]
__device__ float g_P[KSPLIT * BB * NN];   // split-K partials of x @ Wt
__device__ float g_S1[BB * NN];           // S1[b][d] = sum_n states1
__device__ float g_st1[BB * NN * NN];     // states step0, layout [b][n][d]
__device__ float g_st2[BB * NN * NN];     // states step1, layout [b][n][d]
__device__ float g_out[BB * NN];          // out[b][d] = states2[b,d,127]

// ---------------- K1: reduce edge_vectors over j; nsum ----------------
__global__ void k_prep(const float* __restrict__ ev, const float* __restrict__ ns) {
    int bi = blockIdx.x;
    int t  = threadIdx.x;
    if (bi < NN) {
        __shared__ float red[256];
        int i  = bi;
        int n  = t & 127;
        int j0 = (t >> 7) * 64;
        const float* p = ev + (size_t)i * NN * NN + (size_t)j0 * NN + n;
        float acc = 0.f;
        #pragma unroll 16
        for (int j = 0; j < 64; j++) acc += p[j * NN];
        red[t] = acc;
        __syncthreads();
        if (t < NN) g_Q[n * NN + i] = red[t] + red[t + 128];
    } else {
        if (t < NN) {
            float acc = 0.f;
            #pragma unroll 16
            for (int n = 0; n < NN; n++) acc += ns[n * NN + t];
            g_nsum[t] = acc;
        }
    }
}

// ---------------- K2: x_t partials = x @ input_proj_w.T (split-K) ----------------
__global__ void __launch_bounds__(256) k_gemm1(const float* __restrict__ x,
                                               const float* __restrict__ w) {
    __shared__ float xs[32 * 65];
    __shared__ float ws[32 * 65];
    int s  = blockIdx.x;        // k-split
    int db = blockIdx.y;        // d-tile of 32
    int t  = threadIdx.x;
    int k0 = s * KSEG;
    int d0 = db * 32;
    int bq = t & 15, dq = t >> 4;
    float a00 = 0.f, a01 = 0.f, a10 = 0.f, a11 = 0.f;
    for (int kc = 0; kc < KSEG; kc += 64) {
        #pragma unroll
        for (int i = 0; i < 8; i++) {
            int e = t + i * 256;
            int r = e >> 6, c = e & 63;
            xs[r * 65 + c] = x[r * INF + k0 + kc + c];
            ws[r * 65 + c] = w[(d0 + r) * INF + k0 + kc + c];
        }
        __syncthreads();
        #pragma unroll
        for (int k = 0; k < 64; k++) {
            float xb0 = xs[(2 * bq) * 65 + k];
            float xb1 = xs[(2 * bq + 1) * 65 + k];
            float wd0 = ws[(2 * dq) * 65 + k];
            float wd1 = ws[(2 * dq + 1) * 65 + k];
            a00 += xb0 * wd0; a01 += xb0 * wd1;
            a10 += xb1 * wd0; a11 += xb1 * wd1;
        }
        __syncthreads();
    }
    int b0 = 2 * bq, dl = 2 * dq;
    g_P[(s * BB + b0) * NN + d0 + dl]           = a00;
    g_P[(s * BB + b0) * NN + d0 + dl + 1]       = a01;
    g_P[(s * BB + b0 + 1) * NN + d0 + dl]       = a10;
    g_P[(s * BB + b0 + 1) * NN + d0 + dl + 1]   = a11;
}

// ---------------- K3: states init + closed-form S1 ----------------
__global__ void k_init(const float* __restrict__ ns, const float* __restrict__ ib) {
    int b  = blockIdx.x;
    int nq = blockIdx.y;
    int d  = threadIdx.x;
    float xt = ib[d];
    #pragma unroll
    for (int s = 0; s < KSPLIT; s++) xt += g_P[(s * BB + b) * NN + d];
    if (nq == 0) g_S1[b * NN + d] = g_nsum[d] + 128.f * xt;
    int n0 = nq * 32;
    #pragma unroll 8
    for (int n = n0; n < n0 + 32; n++)
        g_st1[(b * NN + n) * NN + d] = ns[n * NN + d] + xt;
}

// ---------------- K4: step 1 (full) : C = st1^T @ Q, scale, mask, relu ----------------
__global__ void __launch_bounds__(256) k_step1() {
    __shared__ float As[32 * 64];
    __shared__ float Qs[32 * 64];
    int b  = blockIdx.x;
    int dt = blockIdx.y;
    int it = blockIdx.z;
    int t  = threadIdx.x;
    int tx = t & 15, ty = t >> 4;
    int i0l = tx * 4, d0l = ty * 4;
    float4 acc0 = make_float4(0, 0, 0, 0);
    float4 acc1 = acc0, acc2 = acc0, acc3 = acc0;
    const float* stb = g_st1 + (size_t)b * NN * NN;
    for (int n0 = 0; n0 < NN; n0 += 32) {
        #pragma unroll
        for (int i = 0; i < 8; i++) {
            int e = t + i * 256;
            int r = e >> 6, c = e & 63;
            As[r * 64 + c] = stb[(n0 + r) * NN + dt * 64 + c];
            Qs[r * 64 + c] = g_Q[(n0 + r) * NN + it * 64 + c];
        }
        __syncthreads();
        #pragma unroll
        for (int k = 0; k < 32; k++) {
            float4 av = *(const float4*)&As[k * 64 + d0l];
            float4 qv = *(const float4*)&Qs[k * 64 + i0l];
            acc0.x += av.x * qv.x; acc0.y += av.y * qv.x; acc0.z += av.z * qv.x; acc0.w += av.w * qv.x;
            acc1.x += av.x * qv.y; acc1.y += av.y * qv.y; acc1.z += av.z * qv.y; acc1.w += av.w * qv.y;
            acc2.x += av.x * qv.z; acc2.y += av.y * qv.z; acc2.z += av.z * qv.z; acc2.w += av.w * qv.z;
            acc3.x += av.x * qv.w; acc3.y += av.y * qv.w; acc3.z += av.z * qv.w; acc3.w += av.w * qv.w;
        }
        __syncthreads();
    }
    float4 s1 = *(const float4*)&g_S1[b * NN + dt * 64 + d0l];
    int dg0 = dt * 64 + d0l;
    float4 av[4] = {acc0, acc1, acc2, acc3};
    #pragma unroll
    for (int ii = 0; ii < 4; ii++) {
        int ig = it * 64 + i0l + ii;
        float4 v = av[ii];
        v.x *= s1.x; v.y *= s1.y; v.z *= s1.z; v.w *= s1.w;
        if (ig == dg0)     v.x = 0.f;
        if (ig == dg0 + 1) v.y = 0.f;
        if (ig == dg0 + 2) v.z = 0.f;
        if (ig == dg0 + 3) v.w = 0.f;
        v.x = fmaxf(v.x, 0.f); v.y = fmaxf(v.y, 0.f);
        v.z = fmaxf(v.z, 0.f); v.w = fmaxf(v.w, 0.f);
        *(float4*)&g_st2[((size_t)b * NN + ig) * NN + dg0] = v;
    }
}

// ---------------- K5: step 2 (only column i=127 needed) ----------------
__global__ void k_step2() {
    int b = blockIdx.x, t = threadIdx.x;
    __shared__ float e127[NN];
    e127[t] = g_Q[t * NN + 127];
    __syncthreads();
    const float* p = g_st2 + (size_t)b * NN * NN + t;
    float c = 0.f, s = 0.f;
    #pragma unroll 8
    for (int n = 0; n < NN; n++) {
        float v = p[n * NN];
        c += v * e127[n];
        s += v;
    }
    float m = c * s;
    if (t == 127) m = 0.f;           // mask[d, i=127] zero when d==127
    g_out[b * NN + t] = fmaxf(m, 0.f);
}

// ---------------- K6: recreation GEMM + scores ----------------
__global__ void __launch_bounds__(256) k_heads(const float* __restrict__ rw,
                                               const float* __restrict__ rb,
                                               const float* __restrict__ sw,
                                               const float* __restrict__ sb,
                                               float* __restrict__ out,
                                               int score_off) {
    int bx = blockIdx.x;
    int t  = threadIdx.x;
    if (bx < 144) {
        __shared__ float os[32 * 129];
        __shared__ float ws[32 * 129];
        int f0 = bx * 32;
        #pragma unroll
        for (int i = 0; i < 16; i++) {
            int e = t + i * 256;
            int r = e >> 7, c = e & 127;
            os[r * 129 + c] = g_out[r * NN + c];
            ws[r * 129 + c] = rw[(f0 + r) * NN + c];
        }
        __syncthreads();
        int bq = t & 15, fq = t >> 4;
        int b0 = 2 * bq, fl = 2 * fq;
        float a00 = 0.f, a01 = 0.f, a10 = 0.f, a11 = 0.f;
        #pragma unroll 8
        for (int k = 0; k < NN; k++) {
            float xb0 = os[b0 * 129 + k];
            float xb1 = os[(b0 + 1) * 129 + k];
            float w0  = ws[fl * 129 + k];
            float w1  = ws[(fl + 1) * 129 + k];
            a00 += xb0 * w0; a01 += xb0 * w1;
            a10 += xb1 * w0; a11 += xb1 * w1;
        }
        float rb0 = rb[f0 + fl], rb1 = rb[f0 + fl + 1];
        out[b0 * INF + f0 + fl]           = a00 + rb0;
        out[b0 * INF + f0 + fl + 1]       = a01 + rb1;
        out[(b0 + 1) * INF + f0 + fl]     = a10 + rb0;
        out[(b0 + 1) * INF + f0 + fl + 1] = a11 + rb1;
    } else {
        if (t < BB) {
            float acc = sb[0];
            #pragma unroll 8
            for (int d = 0; d < NN; d++) acc += g_out[t * NN + d] * sw[d];
            out[score_off + t] = acc;
        }
    }
}

// ---------------- launch ----------------
extern "C" void kernel_launch(void* const* d_in, const int* in_sizes, int n_in,
                              void* d_out, int out_size) {
    const float* x   = (const float*)d_in[0];
    const float* ipw = (const float*)d_in[1];
    const float* ipb = (const float*)d_in[2];
    const float* ns  = (const float*)d_in[3];
    const float* ev  = (const float*)d_in[4];
    const float* rw  = (const float*)d_in[5];
    const float* rb  = (const float*)d_in[6];
    const float* sw  = (const float*)d_in[7];
    const float* sb  = (const float*)d_in[8];
    float* out = (float*)d_out;

    k_prep <<<129, 256>>>(ev, ns);
    k_gemm1<<<dim3(9, 4), 256>>>(x, ipw);
    k_init <<<dim3(32, 4), 128>>>(ns, ipb);
    k_step1<<<dim3(32, 2, 2), 256>>>();
    k_step2<<<32, 128>>>();
    k_heads<<<145, 256>>>(rw, rb, sw, sb, out, out_size - BB);
}

// round 5
// speedup vs baseline: 1.4127x; 1.4127x over previous
#include <cuda_runtime.h>

#define NN   128
#define BB   32
#define INF  4608
#define KSPLIT 36    // 4608 / 128
#define KSEG   128

// ---------------- device scratch ----------------
__device__ float g_Q[NN * NN];            // Q[n][i] = sum_j ev[i][j][n]
__device__ float g_qsum[NN];              // qsum[i] = sum_n Q[n][i]
__device__ float g_nsum[NN];              // nsum[d] = sum_n ns[n][d]
__device__ float g_P[KSPLIT * BB * NN];   // split-K partials of x @ Wt
__device__ float g_M0T[NN * NN];          // M0T[i][d] = sum_n ns[n][d] Q[n][i]
__device__ float g_out[BB * NN];          // out[b][d]

// ---------------- K1: Q = reduce_j(ev), qsum, nsum ----------------
__global__ void k_prep(const float* __restrict__ ev, const float* __restrict__ ns) {
    int bi = blockIdx.x;
    int t  = threadIdx.x;
    __shared__ float red[256];
    if (bi < NN) {
        int i  = bi;
        int n  = t & 127;
        int j0 = (t >> 7) * 64;
        const float* p = ev + (size_t)i * NN * NN + (size_t)j0 * NN + n;
        float acc = 0.f;
        #pragma unroll 16
        for (int j = 0; j < 64; j++) acc += p[j * NN];
        red[t] = acc;
        __syncthreads();
        float qv = 0.f;
        if (t < NN) {
            qv = red[t] + red[t + 128];
            g_Q[n * NN + i] = qv;
        }
        __syncthreads();
        red[t] = (t < NN) ? qv : 0.f;
        __syncthreads();
        #pragma unroll
        for (int off = 64; off > 0; off >>= 1) {
            if (t < off) red[t] += red[t + off];
            __syncthreads();
        }
        if (t == 0) g_qsum[i] = red[0];
    } else {
        if (t < NN) {
            float acc = 0.f;
            #pragma unroll 16
            for (int n = 0; n < NN; n++) acc += ns[n * NN + t];
            g_nsum[t] = acc;
        }
    }
}

// ---------------- K2: x_t partials = x @ input_proj_w.T (split-K, 144 blocks) ----------------
__global__ void __launch_bounds__(256) k_gemm1(const float* __restrict__ x,
                                               const float* __restrict__ w) {
    __shared__ float xs[32 * 65];
    __shared__ float ws[32 * 65];
    int s  = blockIdx.x;        // k-split (36)
    int db = blockIdx.y;        // d-tile of 32 (4)
    int t  = threadIdx.x;
    int k0 = s * KSEG;
    int d0 = db * 32;
    int bq = t & 15, dq = t >> 4;
    float a00 = 0.f, a01 = 0.f, a10 = 0.f, a11 = 0.f;
    for (int kc = 0; kc < KSEG; kc += 64) {
        #pragma unroll
        for (int i = 0; i < 8; i++) {
            int e = t + i * 256;
            int r = e >> 6, c = e & 63;
            xs[r * 65 + c] = x[r * INF + k0 + kc + c];
            ws[r * 65 + c] = w[(d0 + r) * INF + k0 + kc + c];
        }
        __syncthreads();
        #pragma unroll
        for (int k = 0; k < 64; k++) {
            float xb0 = xs[(2 * bq) * 65 + k];
            float xb1 = xs[(2 * bq + 1) * 65 + k];
            float wd0 = ws[(2 * dq) * 65 + k];
            float wd1 = ws[(2 * dq + 1) * 65 + k];
            a00 += xb0 * wd0; a01 += xb0 * wd1;
            a10 += xb1 * wd0; a11 += xb1 * wd1;
        }
        __syncthreads();
    }
    int b0 = 2 * bq, dl = 2 * dq;
    g_P[(s * BB + b0) * NN + d0 + dl]           = a00;
    g_P[(s * BB + b0) * NN + d0 + dl + 1]       = a01;
    g_P[(s * BB + b0 + 1) * NN + d0 + dl]       = a10;
    g_P[(s * BB + b0 + 1) * NN + d0 + dl + 1]   = a11;
}

// ---------------- K3: M0T[i][d] = sum_n ns[n][d] * Q[n][i] (128^3 GEMM) ----------------
__global__ void __launch_bounds__(256) k_M0(const float* __restrict__ ns) {
    __shared__ float As[NN * 32];   // [n][d-sub]
    __shared__ float Qs[NN * 32];   // [n][i-sub]
    int d0 = blockIdx.x * 32;
    int i0 = blockIdx.y * 32;
    int t  = threadIdx.x;
    #pragma unroll
    for (int r0 = 0; r0 < 16; r0++) {
        int e = t + r0 * 256;
        int r = e >> 5, c = e & 31;
        As[r * 32 + c] = ns[r * NN + d0 + c];
        Qs[r * 32 + c] = g_Q[r * NN + i0 + c];
    }
    __syncthreads();
    int tx = t & 15, ty = t >> 4;
    int dl = 2 * tx, il = 2 * ty;
    float a00 = 0.f, a01 = 0.f, a10 = 0.f, a11 = 0.f;
    #pragma unroll 8
    for (int k = 0; k < NN; k++) {
        float A0 = As[k * 32 + dl], A1 = As[k * 32 + dl + 1];
        float Q0 = Qs[k * 32 + il], Q1 = Qs[k * 32 + il + 1];
        a00 += A0 * Q0; a01 += A1 * Q0;
        a10 += A0 * Q1; a11 += A1 * Q1;
    }
    g_M0T[(i0 + il) * NN + d0 + dl]           = a00;
    g_M0T[(i0 + il) * NN + d0 + dl + 1]       = a01;
    g_M0T[(i0 + il + 1) * NN + d0 + dl]       = a10;
    g_M0T[(i0 + il + 1) * NN + d0 + dl + 1]   = a11;
}

// ---------------- K4: fused step1 (closed form) + step2 reduction ----------------
__global__ void k_final(const float* __restrict__ ib) {
    int b = blockIdx.x, d = threadIdx.x;
    __shared__ float q127[NN], qs[NN];
    q127[d] = g_Q[d * NN + 127];
    qs[d]   = g_qsum[d];
    __syncthreads();
    // finalize x_t[b][d]
    float xt = ib[d];
    #pragma unroll
    for (int s = 0; s < KSPLIT; s++) xt += g_P[(s * BB + b) * NN + d];
    float s1 = g_nsum[d] + 128.f * xt;
    // states2[b,d,i] = relu(mask * (M0[d,i] + xt*qsum[i]) * s1), consumed on the fly
    float c = 0.f, ssum = 0.f;
    #pragma unroll 8
    for (int i = 0; i < NN; i++) {
        float v = (g_M0T[i * NN + d] + xt * qs[i]) * s1;
        if (i == d) v = 0.f;
        v = fmaxf(v, 0.f);
        c    += v * q127[i];
        ssum += v;
    }
    float m = c * ssum;
    if (d == 127) m = 0.f;
    g_out[b * NN + d] = fmaxf(m, 0.f);
}

// ---------------- K5: recreation GEMM + scores ----------------
__global__ void __launch_bounds__(256) k_heads(const float* __restrict__ rw,
                                               const float* __restrict__ rb,
                                               const float* __restrict__ sw,
                                               const float* __restrict__ sb,
                                               float* __restrict__ out,
                                               int score_off) {
    int bx = blockIdx.x;
    int t  = threadIdx.x;
    if (bx < 144) {
        __shared__ float os[32 * 129];
        __shared__ float ws[32 * 129];
        int f0 = bx * 32;
        #pragma unroll
        for (int i = 0; i < 16; i++) {
            int e = t + i * 256;
            int r = e >> 7, c = e & 127;
            os[r * 129 + c] = g_out[r * NN + c];
            ws[r * 129 + c] = rw[(f0 + r) * NN + c];
        }
        __syncthreads();
        int bq = t & 15, fq = t >> 4;
        int b0 = 2 * bq, fl = 2 * fq;
        float a00 = 0.f, a01 = 0.f, a10 = 0.f, a11 = 0.f;
        #pragma unroll 8
        for (int k = 0; k < NN; k++) {
            float xb0 = os[b0 * 129 + k];
            float xb1 = os[(b0 + 1) * 129 + k];
            float w0  = ws[fl * 129 + k];
            float w1  = ws[(fl + 1) * 129 + k];
            a00 += xb0 * w0; a01 += xb0 * w1;
            a10 += xb1 * w0; a11 += xb1 * w1;
        }
        float rb0 = rb[f0 + fl], rb1 = rb[f0 + fl + 1];
        out[b0 * INF + f0 + fl]           = a00 + rb0;
        out[b0 * INF + f0 + fl + 1]       = a01 + rb1;
        out[(b0 + 1) * INF + f0 + fl]     = a10 + rb0;
        out[(b0 + 1) * INF + f0 + fl + 1] = a11 + rb1;
    } else {
        if (t < BB) {
            float acc = sb[0];
            #pragma unroll 8
            for (int d = 0; d < NN; d++) acc += g_out[t * NN + d] * sw[d];
            out[score_off + t] = acc;
        }
    }
}

// ---------------- launch ----------------
extern "C" void kernel_launch(void* const* d_in, const int* in_sizes, int n_in,
                              void* d_out, int out_size) {
    const float* x   = (const float*)d_in[0];
    const float* ipw = (const float*)d_in[1];
    const float* ipb = (const float*)d_in[2];
    const float* ns  = (const float*)d_in[3];
    const float* ev  = (const float*)d_in[4];
    const float* rw  = (const float*)d_in[5];
    const float* rb  = (const float*)d_in[6];
    const float* sw  = (const float*)d_in[7];
    const float* sb  = (const float*)d_in[8];
    float* out = (float*)d_out;

    k_prep <<<129, 256>>>(ev, ns);
    k_gemm1<<<dim3(36, 4), 256>>>(x, ipw);
    k_M0   <<<dim3(4, 4), 256>>>(ns);
    k_final<<<32, 128>>>(ipb);
    k_heads<<<145, 256>>>(rw, rb, sw, sb, out, out_size - BB);
}

// round 6
// speedup vs baseline: 2.0467x; 1.4488x over previous
#include <cuda_runtime.h>

#define NN   128
#define BB   32
#define INF  4608
#define KSPLIT 36    // 4608 / 128
#define KSEG   128

// ---------------- device scratch ----------------
__device__ float g_qsum[NN];              // qsum[i] = sum_n Q[n][i]
__device__ float g_q127[NN];              // q127[n] = Q[n][127]
__device__ float g_nsum[NN];              // nsum[d] = sum_n ns[n][d]
__device__ float g_P[KSPLIT * BB * NN];   // split-K partials of x @ Wt
__device__ float g_M0T[NN * NN];          // M0T[i][d] = sum_n ns[n][d] Q[n][i]
__device__ float g_out[BB * NN];          // out[b][d]

// ---------------- K1 (fused): ev-reduce -> qsum/q127/M0T ; nsum ; input GEMM ----------------
__global__ void __launch_bounds__(256) k_fused1(const float* __restrict__ ev,
                                                const float* __restrict__ ns,
                                                const float* __restrict__ x,
                                                const float* __restrict__ w) {
    int bi = blockIdx.x;
    int t  = threadIdx.x;
    if (bi < NN) {
        // ---- per-i: qv[n] = Q[n][i] = sum_j ev[i][j][n]; then qsum, q127, M0T row ----
        __shared__ float red[256];
        __shared__ float qsh[NN];
        __shared__ float pd[256];
        int i  = bi;
        int n  = t & 127;
        int j0 = (t >> 7) * 64;
        const float* p = ev + (size_t)i * NN * NN + (size_t)j0 * NN + n;
        float acc = 0.f;
        #pragma unroll 16
        for (int j = 0; j < 64; j++) acc += p[j * NN];
        red[t] = acc;
        __syncthreads();
        float qv = 0.f;
        if (t < NN) {
            qv = red[t] + red[t + 128];
            qsh[t] = qv;
            if (i == 127) g_q127[t] = qv;   // Q[n][127]
        }
        __syncthreads();
        // qsum[i] = sum_n qv[n]
        red[t] = (t < NN) ? qv : 0.f;
        __syncthreads();
        #pragma unroll
        for (int off = 64; off > 0; off >>= 1) {
            if (t < off) red[t] += red[t + off];
            __syncthreads();
        }
        if (t == 0) g_qsum[i] = red[0];
        // M0T[i][d] = sum_n qv[n] * ns[n][d]  (split n across 2 halves)
        int d = t & 127, h = t >> 7;
        float m = 0.f;
        int n0 = h * 64;
        #pragma unroll 8
        for (int k = 0; k < 64; k++) m += qsh[n0 + k] * ns[(n0 + k) * NN + d];
        pd[t] = m;
        __syncthreads();
        if (t < NN) g_M0T[i * NN + t] = pd[t] + pd[t + 128];
    } else if (bi == NN) {
        // ---- nsum[d] = sum_n ns[n][d] ----
        if (t < NN) {
            float acc = 0.f;
            #pragma unroll 16
            for (int n = 0; n < NN; n++) acc += ns[n * NN + t];
            g_nsum[t] = acc;
        }
    } else {
        // ---- input GEMM split-K: idx in [0,144) -> (s, db) ----
        __shared__ float xs[32 * 65];
        __shared__ float ws[32 * 65];
        int idx = bi - NN - 1;
        int s   = idx >> 2;          // 0..35
        int db  = idx & 3;           // 0..3
        int k0  = s * KSEG;
        int d0  = db * 32;
        int bq = t & 15, dq = t >> 4;
        float a00 = 0.f, a01 = 0.f, a10 = 0.f, a11 = 0.f;
        for (int kc = 0; kc < KSEG; kc += 64) {
            #pragma unroll
            for (int i = 0; i < 8; i++) {
                int e = t + i * 256;
                int r = e >> 6, c = e & 63;
                xs[r * 65 + c] = x[r * INF + k0 + kc + c];
                ws[r * 65 + c] = w[(d0 + r) * INF + k0 + kc + c];
            }
            __syncthreads();
            #pragma unroll
            for (int k = 0; k < 64; k++) {
                float xb0 = xs[(2 * bq) * 65 + k];
                float xb1 = xs[(2 * bq + 1) * 65 + k];
                float wd0 = ws[(2 * dq) * 65 + k];
                float wd1 = ws[(2 * dq + 1) * 65 + k];
                a00 += xb0 * wd0; a01 += xb0 * wd1;
                a10 += xb1 * wd0; a11 += xb1 * wd1;
            }
            __syncthreads();
        }
        int b0 = 2 * bq, dl = 2 * dq;
        g_P[(s * BB + b0) * NN + d0 + dl]           = a00;
        g_P[(s * BB + b0) * NN + d0 + dl + 1]       = a01;
        g_P[(s * BB + b0 + 1) * NN + d0 + dl]       = a10;
        g_P[(s * BB + b0 + 1) * NN + d0 + dl + 1]   = a11;
    }
}

// ---------------- K2: fused step1 closed-form + step2 reduction (8-way i-split) ----------------
__global__ void __launch_bounds__(1024) k_final(const float* __restrict__ ib) {
    int b  = blockIdx.x;
    int t  = threadIdx.x;
    int d  = t & 127;
    int iq = t >> 7;                 // 0..7
    __shared__ float qs_s[NN], q127_s[NN], xt_s[NN], s1_s[NN];
    __shared__ float pc[8][NN], ps[8][NN];
    // split-K finalize of x_t spread across octants: 5 loads/thread max
    float xp = 0.f;
    #pragma unroll
    for (int s = iq; s < KSPLIT; s += 8) xp += g_P[(s * BB + b) * NN + d];
    pc[iq][d] = xp;
    if (t < NN) {
        qs_s[t]   = g_qsum[t];
        q127_s[t] = g_q127[t];
    }
    __syncthreads();
    if (t < NN) {
        float xt = ib[t];
        #pragma unroll
        for (int q = 0; q < 8; q++) xt += pc[q][t];
        xt_s[t] = xt;
        s1_s[t] = g_nsum[t] + 128.f * xt;
    }
    __syncthreads();
    float xt = xt_s[d], s1 = s1_s[d];
    // states2[b,d,i] = relu(mask * (M0T[i,d] + xt*qsum[i]) * s1), consumed on the fly
    float c = 0.f, ss = 0.f;
    int i0 = iq * 16;
    #pragma unroll
    for (int k = 0; k < 16; k++) {
        int i = i0 + k;
        float v = (g_M0T[i * NN + d] + xt * qs_s[i]) * s1;
        v = (i == d) ? 0.f : fmaxf(v, 0.f);
        c  += v * q127_s[i];
        ss += v;
    }
    pc[iq][d] = c; ps[iq][d] = ss;
    __syncthreads();
    if (t < NN) {
        float C = 0.f, S = 0.f;
        #pragma unroll
        for (int q = 0; q < 8; q++) { C += pc[q][d]; S += ps[q][d]; }
        float m = C * S;
        if (d == 127) m = 0.f;
        g_out[b * NN + d] = fmaxf(m, 0.f);
    }
}

// ---------------- K3: recreation GEMM + scores ----------------
__global__ void __launch_bounds__(256) k_heads(const float* __restrict__ rw,
                                               const float* __restrict__ rb,
                                               const float* __restrict__ sw,
                                               const float* __restrict__ sb,
                                               float* __restrict__ out,
                                               int score_off) {
    int bx = blockIdx.x;
    int t  = threadIdx.x;
    if (bx < 144) {
        __shared__ float os[32 * 129];
        __shared__ float ws[32 * 129];
        int f0 = bx * 32;
        #pragma unroll
        for (int i = 0; i < 16; i++) {
            int e = t + i * 256;
            int r = e >> 7, c = e & 127;
            os[r * 129 + c] = g_out[r * NN + c];
            ws[r * 129 + c] = rw[(f0 + r) * NN + c];
        }
        __syncthreads();
        int bq = t & 15, fq = t >> 4;
        int b0 = 2 * bq, fl = 2 * fq;
        float a00 = 0.f, a01 = 0.f, a10 = 0.f, a11 = 0.f;
        #pragma unroll 8
        for (int k = 0; k < NN; k++) {
            float xb0 = os[b0 * 129 + k];
            float xb1 = os[(b0 + 1) * 129 + k];
            float w0  = ws[fl * 129 + k];
            float w1  = ws[(fl + 1) * 129 + k];
            a00 += xb0 * w0; a01 += xb0 * w1;
            a10 += xb1 * w0; a11 += xb1 * w1;
        }
        float rb0 = rb[f0 + fl], rb1 = rb[f0 + fl + 1];
        out[b0 * INF + f0 + fl]           = a00 + rb0;
        out[b0 * INF + f0 + fl + 1]       = a01 + rb1;
        out[(b0 + 1) * INF + f0 + fl]     = a10 + rb0;
        out[(b0 + 1) * INF + f0 + fl + 1] = a11 + rb1;
    } else {
        if (t < BB) {
            float acc = sb[0];
            #pragma unroll 8
            for (int d = 0; d < NN; d++) acc += g_out[t * NN + d] * sw[d];
            out[score_off + t] = acc;
        }
    }
}

// ---------------- launch ----------------
extern "C" void kernel_launch(void* const* d_in, const int* in_sizes, int n_in,
                              void* d_out, int out_size) {
    const float* x   = (const float*)d_in[0];
    const float* ipw = (const float*)d_in[1];
    const float* ipb = (const float*)d_in[2];
    const float* ns  = (const float*)d_in[3];
    const float* ev  = (const float*)d_in[4];
    const float* rw  = (const float*)d_in[5];
    const float* rb  = (const float*)d_in[6];
    const float* sw  = (const float*)d_in[7];
    const float* sb  = (const float*)d_in[8];
    float* out = (float*)d_out;

    k_fused1<<<NN + 1 + 144, 256>>>(ev, ns, x, ipw);
    k_final <<<BB, 1024>>>(ipb);
    k_heads <<<145, 256>>>(rw, rb, sw, sb, out, out_size - BB);
}

// round 7
// speedup vs baseline: 2.0716x; 1.0122x over previous
#include <cuda_runtime.h>

#define NN   128
#define BB   32
#define INF  4608
#define KSPLIT 36    // 4608 / 128
#define KSEG   128

// ---------------- device scratch ----------------
__device__ float g_qsum[NN];              // qsum[i] = sum_n Q[n][i]
__device__ float g_q127[NN];              // q127[n] = Q[n][127]
__device__ float g_nsum[NN];              // nsum[d] = sum_n ns[n][d]
__device__ float g_P[KSPLIT * BB * NN];   // split-K partials of x @ Wt
__device__ float g_M0T[NN * NN];          // M0T[i][d] = sum_n ns[n][d] Q[n][i]
__device__ float g_out[BB * NN];          // out[b][d]

// ---------------- K1 (fused): ev-reduce -> qsum/q127/M0T ; nsum ; input GEMM ----------------
__global__ void __launch_bounds__(256) k_fused1(const float* __restrict__ ev,
                                                const float* __restrict__ ns,
                                                const float* __restrict__ x,
                                                const float* __restrict__ w) {
    int bi = blockIdx.x;
    int t  = threadIdx.x;
    if (bi < NN) {
        // ---- per-i: qv[n] = Q[n][i] = sum_j ev[i][j][n] (float4 over n) ----
        __shared__ float4 sred[256];
        __shared__ float  qsh[NN];
        __shared__ float  pd[256];
        int i  = bi;
        int n4 = t & 31;            // float4 index over n (32 x 4 = 128)
        int j0 = t >> 5;            // 0..7
        const float4* p4 = (const float4*)(ev + (size_t)i * NN * NN);  // [128][32]
        float4 a = make_float4(0.f, 0.f, 0.f, 0.f);
        #pragma unroll
        for (int j = j0; j < NN; j += 8) {
            float4 v = p4[j * 32 + n4];
            a.x += v.x; a.y += v.y; a.z += v.z; a.w += v.w;
        }
        sred[t] = a;
        __syncthreads();
        if (j0 < 4) {
            float4 b = sred[t + 128];
            a.x += b.x; a.y += b.y; a.z += b.z; a.w += b.w;
            sred[t] = a;
        }
        __syncthreads();
        if (j0 < 2) {
            float4 b = sred[t + 64];
            a.x += b.x; a.y += b.y; a.z += b.z; a.w += b.w;
            sred[t] = a;
        }
        __syncthreads();
        if (j0 == 0) {
            float4 b = sred[t + 32];
            a.x += b.x; a.y += b.y; a.z += b.z; a.w += b.w;
            qsh[4 * n4 + 0] = a.x; qsh[4 * n4 + 1] = a.y;
            qsh[4 * n4 + 2] = a.z; qsh[4 * n4 + 3] = a.w;
            if (i == 127) ((float4*)g_q127)[n4] = a;       // Q[n][127]
            float s = a.x + a.y + a.z + a.w;
            #pragma unroll
            for (int off = 16; off > 0; off >>= 1)
                s += __shfl_xor_sync(0xffffffffu, s, off);
            if (n4 == 0) g_qsum[i] = s;
        }
        __syncthreads();
        // M0T[i][d] = sum_n qsh[n] * ns[n][d]  (split n across 2 halves)
        int d = t & 127, h = t >> 7;
        float m = 0.f;
        int nb = h * 64;
        #pragma unroll 8
        for (int k = 0; k < 64; k++) m += qsh[nb + k] * ns[(nb + k) * NN + d];
        pd[t] = m;
        __syncthreads();
        if (t < NN) g_M0T[i * NN + t] = pd[t] + pd[t + 128];
    } else if (bi == NN) {
        // ---- nsum[d] = sum_n ns[n][d] ----
        if (t < NN) {
            float acc = 0.f;
            #pragma unroll 16
            for (int n = 0; n < NN; n++) acc += ns[n * NN + t];
            g_nsum[t] = acc;
        }
    } else {
        // ---- input GEMM split-K: idx in [0,144) -> (s, db) ----
        __shared__ float xs[32 * 65];
        __shared__ float ws[32 * 65];
        int idx = bi - NN - 1;
        int s   = idx >> 2;          // 0..35
        int db  = idx & 3;           // 0..3
        int k0  = s * KSEG;
        int d0  = db * 32;
        int bq = t & 15, dq = t >> 4;
        float a00 = 0.f, a01 = 0.f, a10 = 0.f, a11 = 0.f;
        for (int kc = 0; kc < KSEG; kc += 64) {
            #pragma unroll
            for (int i = 0; i < 2; i++) {
                int e  = t + i * 256;          // 512 float4 = 32 rows x 16 f4
                int r  = e >> 4, c4 = e & 15;
                float4 xv = *(const float4*)&x[r * INF + k0 + kc + c4 * 4];
                float4 wv = *(const float4*)&w[(d0 + r) * INF + k0 + kc + c4 * 4];
                int o = r * 65 + c4 * 4;
                xs[o + 0] = xv.x; xs[o + 1] = xv.y; xs[o + 2] = xv.z; xs[o + 3] = xv.w;
                ws[o + 0] = wv.x; ws[o + 1] = wv.y; ws[o + 2] = wv.z; ws[o + 3] = wv.w;
            }
            __syncthreads();
            #pragma unroll
            for (int k = 0; k < 64; k++) {
                float xb0 = xs[(2 * bq) * 65 + k];
                float xb1 = xs[(2 * bq + 1) * 65 + k];
                float wd0 = ws[(2 * dq) * 65 + k];
                float wd1 = ws[(2 * dq + 1) * 65 + k];
                a00 += xb0 * wd0; a01 += xb0 * wd1;
                a10 += xb1 * wd0; a11 += xb1 * wd1;
            }
            __syncthreads();
        }
        int b0 = 2 * bq, dl = 2 * dq;
        g_P[(s * BB + b0) * NN + d0 + dl]           = a00;
        g_P[(s * BB + b0) * NN + d0 + dl + 1]       = a01;
        g_P[(s * BB + b0 + 1) * NN + d0 + dl]       = a10;
        g_P[(s * BB + b0 + 1) * NN + d0 + dl + 1]   = a11;
    }
}

// ---------------- K2: fused step1 closed-form + step2 reduction (8-way i-split) ----------------
__global__ void __launch_bounds__(1024) k_final(const float* __restrict__ ib) {
    int b  = blockIdx.x;
    int t  = threadIdx.x;
    int d  = t & 127;
    int iq = t >> 7;                 // 0..7
    __shared__ float qs_s[NN], q127_s[NN], xt_s[NN], s1_s[NN];
    __shared__ float pc[8][NN], ps[8][NN];
    float xp = 0.f;
    #pragma unroll
    for (int s = iq; s < KSPLIT; s += 8) xp += g_P[(s * BB + b) * NN + d];
    pc[iq][d] = xp;
    if (t < NN) {
        qs_s[t]   = g_qsum[t];
        q127_s[t] = g_q127[t];
    }
    __syncthreads();
    if (t < NN) {
        float xt = ib[t];
        #pragma unroll
        for (int q = 0; q < 8; q++) xt += pc[q][t];
        xt_s[t] = xt;
        s1_s[t] = g_nsum[t] + 128.f * xt;
    }
    __syncthreads();
    float xt = xt_s[d], s1 = s1_s[d];
    float c = 0.f, ss = 0.f;
    int i0 = iq * 16;
    #pragma unroll
    for (int k = 0; k < 16; k++) {
        int i = i0 + k;
        float v = (g_M0T[i * NN + d] + xt * qs_s[i]) * s1;
        v = (i == d) ? 0.f : fmaxf(v, 0.f);
        c  += v * q127_s[i];
        ss += v;
    }
    pc[iq][d] = c; ps[iq][d] = ss;
    __syncthreads();
    if (t < NN) {
        float C = 0.f, S = 0.f;
        #pragma unroll
        for (int q = 0; q < 8; q++) { C += pc[q][d]; S += ps[q][d]; }
        float m = C * S;
        if (d == 127) m = 0.f;
        g_out[b * NN + d] = fmaxf(m, 0.f);
    }
}

// ---------------- K3: recreation GEMM + scores ----------------
__global__ void __launch_bounds__(256) k_heads(const float* __restrict__ rw,
                                               const float* __restrict__ rb,
                                               const float* __restrict__ sw,
                                               const float* __restrict__ sb,
                                               float* __restrict__ out,
                                               int score_off) {
    int bx = blockIdx.x;
    int t  = threadIdx.x;
    if (bx < 144) {
        __shared__ float os[32 * 129];
        __shared__ float ws[32 * 129];
        int f0 = bx * 32;
        #pragma unroll
        for (int i = 0; i < 4; i++) {
            int e  = t + i * 256;          // 1024 float4 = 32 rows x 32 f4
            int r  = e >> 5, c4 = e & 31;
            float4 ov = ((const float4*)&g_out[r * NN])[c4];
            float4 wv = ((const float4*)&rw[(size_t)(f0 + r) * NN])[c4];
            int o = r * 129 + c4 * 4;
            os[o + 0] = ov.x; os[o + 1] = ov.y; os[o + 2] = ov.z; os[o + 3] = ov.w;
            ws[o + 0] = wv.x; ws[o + 1] = wv.y; ws[o + 2] = wv.z; ws[o + 3] = wv.w;
        }
        __syncthreads();
        int bq = t & 15, fq = t >> 4;
        int b0 = 2 * bq, fl = 2 * fq;
        float a00 = 0.f, a01 = 0.f, a10 = 0.f, a11 = 0.f;
        #pragma unroll 8
        for (int k = 0; k < NN; k++) {
            float xb0 = os[b0 * 129 + k];
            float xb1 = os[(b0 + 1) * 129 + k];
            float w0  = ws[fl * 129 + k];
            float w1  = ws[(fl + 1) * 129 + k];
            a00 += xb0 * w0; a01 += xb0 * w1;
            a10 += xb1 * w0; a11 += xb1 * w1;
        }
        float rb0 = rb[f0 + fl], rb1 = rb[f0 + fl + 1];
        out[b0 * INF + f0 + fl]           = a00 + rb0;
        out[b0 * INF + f0 + fl + 1]       = a01 + rb1;
        out[(b0 + 1) * INF + f0 + fl]     = a10 + rb0;
        out[(b0 + 1) * INF + f0 + fl + 1] = a11 + rb1;
    } else {
        if (t < BB) {
            float acc = sb[0];
            #pragma unroll 8
            for (int d = 0; d < NN; d++) acc += g_out[t * NN + d] * sw[d];
            out[score_off + t] = acc;
        }
    }
}

// ---------------- launch ----------------
extern "C" void kernel_launch(void* const* d_in, const int* in_sizes, int n_in,
                              void* d_out, int out_size) {
    const float* x   = (const float*)d_in[0];
    const float* ipw = (const float*)d_in[1];
    const float* ipb = (const float*)d_in[2];
    const float* ns  = (const float*)d_in[3];
    const float* ev  = (const float*)d_in[4];
    const float* rw  = (const float*)d_in[5];
    const float* rb  = (const float*)d_in[6];
    const float* sw  = (const float*)d_in[7];
    const float* sb  = (const float*)d_in[8];
    float* out = (float*)d_out;

    k_fused1<<<NN + 1 + 144, 256>>>(ev, ns, x, ipw);
    k_final <<<BB, 1024>>>(ipb);
    k_heads <<<145, 256>>>(rw, rb, sw, sb, out, out_size - BB);
}